// round 5
// baseline (speedup 1.0000x reference)
#include <cuda_runtime.h>
#include <math.h>

#define B_ 8
#define C_ 128
#define H_ 256
#define W_ 256
#define HW (H_*W_)

// ----------------------------- device scratch -----------------------------
__device__ __align__(16) float g_actv[(size_t)B_*C_*HW];   // 268 MB actv
__device__ float g_nT[(size_t)B_*HW];                      // transposed noise [b][h][w]
__device__ float g_mean[B_*C_];
__device__ float g_rstd[B_*C_];
__device__ float g_mu[B_*20*64];                           // row j=19 = zeros
__device__ __align__(16) float g_G2[B_*20*9*C_*2];         // [b][j][tap][co][{g,b}]
__device__ __align__(16) float g_G4[B_*20*16*C_*2];        // [b][j][ph][pw][u][v][co][{g,b}]
__device__ unsigned char g_cls[B_*128*128];
__device__ __align__(16) float g_B1[171*128];              // [j*9+t][co]
__device__ __align__(16) float g_B2[1152*256];             // [ci*9+t][co*2+sel]
__device__ float g_Cg[C_], g_Cb[C_], g_scal[2];

// ----------------------------- helpers -----------------------------
__device__ __forceinline__ unsigned long long fma2(unsigned long long a,
                                                   unsigned long long b,
                                                   unsigned long long c) {
    unsigned long long d;
    asm("fma.rn.f32x2 %0, %1, %2, %3;" : "=l"(d) : "l"(a), "l"(b), "l"(c));
    return d;
}
__device__ __forceinline__ unsigned long long pack2(float x, float y) {
    unsigned long long d;
    asm("mov.b64 %0, {%1, %2};" : "=l"(d) : "f"(x), "f"(y));
    return d;
}

// ----------------------------- prep kernels -----------------------------
__global__ void k_scal(const float* bg, const float* bb, const float* cgb,
                       const float* cbb, const float* sgb, const float* sbb) {
    int co = threadIdx.x;
    float ga = 1.f / (1.f + expf(-bg[0]));
    float ba = 1.f / (1.f + expf(-bb[0]));
    g_Cg[co] = ga * cgb[co] + (1.f - ga) * sgb[co];
    g_Cb[co] = ba * cbb[co] + (1.f - ba) * sbb[co];
    if (co == 0) { g_scal[0] = ga; g_scal[1] = ba; }
}

__global__ void k_mu(const float* sc, const float* fcw, const float* fcb) {
    int bj = blockIdx.x;               // 160 = b*20+j
    int b = bj / 20, j = bj - b * 20;
    int o = threadIdx.x;               // 64
    float r = 0.f;
    if (j < 19) {
        const float* s = sc + (b * 19 + j) * 64;
        const float* w = fcw + (j * 64 + o) * 64;
        #pragma unroll 8
        for (int i = 0; i < 64; i++) r = fmaf(s[i], w[i], r);
        r += fcb[j * 64 + o];
        r = fmaxf(r, 0.f);
    }
    g_mu[bj * 64 + o] = r;
}

__global__ void k_cls(const float* segmap) {
    int idx = blockIdx.x * 256 + threadIdx.x;
    if (idx >= B_ * 128 * 128) return;
    int b = idx >> 14, p = idx & 16383;
    int cls = 19;
    for (int j = 18; j >= 0; j--) {
        if (segmap[(((size_t)b * 19 + j) << 14) + p] > 0.f) { cls = j; break; }
    }
    g_cls[idx] = (unsigned char)cls;
}

__global__ void k_w1(const float* ssw) {  // spade_shared_w [co][j][t] -> g_B1[j*9+t][co]
    int idx = blockIdx.x * 256 + threadIdx.x;
    if (idx >= 171 * 128) return;
    int k = idx >> 7, co = idx & 127;
    int j = k / 9, t = k - j * 9;
    g_B1[idx] = ssw[(co * 19 + j) * 9 + t];
}

__global__ void k_w2(const float* gw, const float* bw) {  // -> g_B2[ci*9+t][co*2+sel]
    int idx = blockIdx.x * 256 + threadIdx.x;
    if (idx >= 1152 * 256) return;
    int k = idx >> 8, n = idx & 255;
    int ci = k / 9, t = k - ci * 9;
    int co = n >> 1;
    const float* w = (n & 1) ? bw : gw;
    g_B2[idx] = w[(co * 128 + ci) * 9 + t];
}

__global__ void k_ntr(const float* noise) {  // g_nT[b][h][w] = noise[b][w][h]
    __shared__ float t[32][33];
    int b = blockIdx.z;
    int w0 = blockIdx.x * 32, h0 = blockIdx.y * 32;
    int tx = threadIdx.x, ty = threadIdx.y;  // 32x8
    for (int i = 0; i < 32; i += 8)
        t[ty + i][tx] = noise[((size_t)b * 256 + w0 + ty + i) * 256 + h0 + tx];
    __syncthreads();
    for (int i = 0; i < 32; i += 8)
        g_nT[((size_t)b * 256 + h0 + ty + i) * 256 + w0 + tx] = t[tx][ty + i];
}

__global__ __launch_bounds__(256) void k_stats(const float* x, const float* nvar) {
    int bc = blockIdx.x;             // 1024
    int b = bc >> 7, c = bc & 127;
    float nv = nvar[c];
    const float* xb = x + (size_t)bc * HW;
    const float* nb = g_nT + (size_t)b * HW;
    float s = 0.f, q = 0.f;
    for (int i = threadIdx.x; i < HW; i += 256) {
        float v = xb[i] + nb[i] * nv;
        s += v; q = fmaf(v, v, q);
    }
    __shared__ float ss[8], sq[8];
    #pragma unroll
    for (int o = 16; o; o >>= 1) {
        s += __shfl_xor_sync(0xffffffffu, s, o);
        q += __shfl_xor_sync(0xffffffffu, q, o);
    }
    int wid = threadIdx.x >> 5, lane = threadIdx.x & 31;
    if (!lane) { ss[wid] = s; sq[wid] = q; }
    __syncthreads();
    if (threadIdx.x == 0) {
        float S = 0.f, Q = 0.f;
        #pragma unroll
        for (int k = 0; k < 8; k++) { S += ss[k]; Q += sq[k]; }
        float m = S * (1.f / HW);
        float var = Q * (1.f / HW) - m * m;
        g_mean[bc] = m;
        g_rstd[bc] = rsqrtf(var + 1e-5f);
    }
}

__global__ __launch_bounds__(128) void k_lut1(const float* gw, const float* bw) {
    int bj = blockIdx.x;    // 160
    int co = threadIdx.x;   // 128
    __shared__ float mu_s[64];
    if (co < 64) mu_s[co] = g_mu[bj * 64 + co];
    __syncthreads();
    for (int t = 0; t < 9; t++) {
        float sg = 0.f, sb = 0.f;
        #pragma unroll 8
        for (int ci = 0; ci < 64; ci++) {
            float m = mu_s[ci];
            sg = fmaf(gw[(co * 64 + ci) * 9 + t], m, sg);
            sb = fmaf(bw[(co * 64 + ci) * 9 + t], m, sb);
        }
        int o = ((bj * 9 + t) * 128 + co) * 2;
        g_G2[o] = sg; g_G2[o + 1] = sb;
    }
}

__global__ __launch_bounds__(256) void k_lut2() {
    int bj = blockIdx.x;    // 160
    int n = threadIdx.x;    // 256
    const float* G = g_G2 + (size_t)bj * 9 * 256;
    float* O = g_G4 + (size_t)bj * 16 * 256;
    for (int ph = 0; ph < 2; ph++)
    for (int pw = 0; pw < 2; pw++)
    for (int u = 0; u < 2; u++)
    for (int v = 0; v < 2; v++) {
        int rlo = (u == 0) ? 0 : (ph == 0 ? 1 : 2);
        int rhi = (u == 0) ? (ph == 0 ? 0 : 1) : 2;
        int clo = (v == 0) ? 0 : (pw == 0 ? 1 : 2);
        int chi = (v == 0) ? (pw == 0 ? 0 : 1) : 2;
        float s = 0.f;
        for (int dy = rlo; dy <= rhi; dy++)
            for (int dx = clo; dx <= chi; dx++)
                s += G[(dy * 3 + dx) * 256 + n];
        O[(((ph * 2 + pw) * 2 + u) * 2 + v) * 256 + n] = s;
    }
}

// ----------------------------- stage A: actv conv (19 -> 128) -----------------------------
__global__ __launch_bounds__(256, 2) void k_actv(const float* segmap, const float* ssb) {
    __shared__ float Sh[19][4][10];
    __shared__ __align__(16) float Bsj[9][128];
    int b = blockIdx.z;
    int x0 = blockIdx.x * 16, y0 = blockIdx.y * 4;
    int tid = threadIdx.x;
    int tx = tid & 15, ty = tid >> 4;
    int r = ty >> 2, c = (ty & 3) * 4;

    // half-res seg tile (covers full-res halo [y0-1, y0+4] x [x0-1, x0+16])
    int hb = (y0 >> 1) - 1, cbh = (x0 >> 1) - 1;
    for (int idx = tid; idx < 19 * 40; idx += 256) {
        int j = idx / 40, pos = idx - j * 40;
        int hr = pos / 10, hc = pos - hr * 10;
        int gy = hb + hr, gx = cbh + hc;
        float v = 0.f;
        if ((unsigned)gy < 128u && (unsigned)gx < 128u)
            v = segmap[(((size_t)b * 19 + j) << 14) + gy * 128 + gx];
        Sh[j][hr][hc] = v;
    }

    int hrw[3], hcc[6];
    #pragma unroll
    for (int k = 0; k < 3; k++) hrw[k] = ((r + k - 1) >> 1) + 1;
    #pragma unroll
    for (int k = 0; k < 6; k++) hcc[k] = ((c + k - 1) >> 1) + 1;

    unsigned long long acc[4][4];
    #pragma unroll
    for (int p = 0; p < 4; p++)
        #pragma unroll
        for (int q = 0; q < 4; q++) acc[p][q] = 0ull;

    for (int j = 0; j < 19; j++) {
        __syncthreads();
        for (int idx = tid; idx < 1152; idx += 256)
            ((float*)Bsj)[idx] = g_B1[j * 1152 + idx];
        __syncthreads();
        #pragma unroll
        for (int t = 0; t < 9; t++) {
            const int tdy = t / 3, tdx = t - tdy * 3;
            unsigned long long Ap[4];
            #pragma unroll
            for (int i = 0; i < 4; i++) {
                float a = Sh[j][hrw[tdy]][hcc[tdx + i]];
                Ap[i] = pack2(a, a);
            }
            ulonglong2 b0 = *(const ulonglong2*)&Bsj[t][tx * 4];
            ulonglong2 b1 = *(const ulonglong2*)&Bsj[t][tx * 4 + 64];
            #pragma unroll
            for (int p = 0; p < 4; p++) {
                acc[p][0] = fma2(Ap[p], b0.x, acc[p][0]);
                acc[p][1] = fma2(Ap[p], b0.y, acc[p][1]);
                acc[p][2] = fma2(Ap[p], b1.x, acc[p][2]);
                acc[p][3] = fma2(Ap[p], b1.y, acc[p][3]);
            }
        }
    }

    int y = y0 + r, xg0 = x0 + c;
    #pragma unroll
    for (int q = 0; q < 4; q++) {
        int co0 = (q < 2) ? (tx * 4 + q * 2) : (tx * 4 + 64 + (q - 2) * 2);
        #pragma unroll
        for (int h2 = 0; h2 < 2; h2++) {
            int co = co0 + h2;
            float bias = ssb[co];
            float4 o;
            float* op = (float*)&o;
            #pragma unroll
            for (int p = 0; p < 4; p++) {
                unsigned long long v = acc[p][q];
                unsigned w32 = h2 ? (unsigned)(v >> 32) : (unsigned)v;
                op[p] = fmaxf(__uint_as_float(w32) + bias, 0.f);
            }
            *(float4*)&g_actv[(((size_t)b * 128 + co) * 256 + y) * 256 + xg0] = o;
        }
    }
}

// ----------------------------- stage B: main fused GEMM + epilogue -----------------------------
__global__ __launch_bounds__(256, 2) void k_main(const float* x, const float* nvar,
                                                 float* out) {
    __shared__ float As[16][108];                 // [ci][6*18] halo tile
    __shared__ __align__(16) float Bs[16][256];   // [ci][co*2+sel]
    int b = blockIdx.z;
    int x0 = blockIdx.x * 16, y0 = blockIdx.y * 4;
    int tid = threadIdx.x;
    int tx = tid & 15, ty = tid >> 4;
    int r = ty >> 2, c = (ty & 3) * 4;

    unsigned long long acc[4][8];
    #pragma unroll
    for (int p = 0; p < 4; p++)
        #pragma unroll
        for (int q = 0; q < 8; q++) acc[p][q] = 0ull;

    for (int ch = 0; ch < 8; ch++) {
        int ci0 = ch * 16;
        __syncthreads();
        for (int idx = tid; idx < 16 * 108; idx += 256) {
            int lci = idx / 108, pos = idx - lci * 108;
            int rr = pos / 18, cc = pos - rr * 18;
            int gy = y0 - 1 + rr, gx = x0 - 1 + cc;
            float v = 0.f;
            if ((unsigned)gy < 256u && (unsigned)gx < 256u)
                v = g_actv[(((size_t)b * 128 + ci0 + lci) * 256 + gy) * 256 + gx];
            As[lci][pos] = v;
        }
        for (int t = 0; t < 9; t++) {
            __syncthreads();
            {
                int kk = tid >> 4, l16 = tid & 15;
                const float* src = &g_B2[(size_t)((ci0 + kk) * 9 + t) * 256];
                #pragma unroll
                for (int jj = 0; jj < 4; jj++) {
                    int col = l16 * 4 + jj * 64;
                    *(float4*)&Bs[kk][col] = *(const float4*)&src[col];
                }
            }
            __syncthreads();
            int tdy = t / 3, tdx = t - tdy * 3;
            int abase = (r + tdy) * 18 + c + tdx;
            #pragma unroll
            for (int kk = 0; kk < 16; kk++) {
                const float* ar = &As[kk][abase];
                unsigned long long Ap[4];
                #pragma unroll
                for (int i = 0; i < 4; i++) { float a = ar[i]; Ap[i] = pack2(a, a); }
                ulonglong2 b0 = *(const ulonglong2*)&Bs[kk][tx * 4];
                ulonglong2 b1 = *(const ulonglong2*)&Bs[kk][tx * 4 + 64];
                ulonglong2 b2 = *(const ulonglong2*)&Bs[kk][tx * 4 + 128];
                ulonglong2 b3 = *(const ulonglong2*)&Bs[kk][tx * 4 + 192];
                #pragma unroll
                for (int p = 0; p < 4; p++) {
                    acc[p][0] = fma2(Ap[p], b0.x, acc[p][0]);
                    acc[p][1] = fma2(Ap[p], b0.y, acc[p][1]);
                    acc[p][2] = fma2(Ap[p], b1.x, acc[p][2]);
                    acc[p][3] = fma2(Ap[p], b1.y, acc[p][3]);
                    acc[p][4] = fma2(Ap[p], b2.x, acc[p][4]);
                    acc[p][5] = fma2(Ap[p], b2.y, acc[p][5]);
                    acc[p][6] = fma2(Ap[p], b3.x, acc[p][6]);
                    acc[p][7] = fma2(Ap[p], b3.y, acc[p][7]);
                }
            }
        }
    }

    // ---------------- fused epilogue ----------------
    float ga = g_scal[0], ba = g_scal[1];
    int y = y0 + r;
    int xg0 = x0 + c;
    int ph = y & 1;
    int r0 = (y - 1) >> 1;

    unsigned gb[4][4];   // per pixel, per (u,v): G4 row base (floats)
    #pragma unroll
    for (int i = 0; i < 4; i++) {
        int xg = xg0 + i;
        int pw = xg & 1;
        int c0 = (xg - 1) >> 1;
        #pragma unroll
        for (int u = 0; u < 2; u++)
            #pragma unroll
            for (int v = 0; v < 2; v++) {
                int cy = r0 + u, cx = c0 + v;
                int cls = 19;
                if ((unsigned)cy < 128u && (unsigned)cx < 128u)
                    cls = g_cls[((size_t)b << 14) + cy * 128 + cx];
                unsigned row = ((((unsigned)(b * 20 + cls) * 2 + ph) * 2 + pw) * 2 + u) * 2 + v;
                gb[i][u * 2 + v] = row * 256u;
            }
    }
    float nz[4];
    #pragma unroll
    for (int i = 0; i < 4; i++) nz[i] = g_nT[((size_t)b * 256 + y) * 256 + xg0 + i];

    #pragma unroll
    for (int q = 0; q < 8; q++) {
        int co = tx * 2 + (q >> 1) * 32 + (q & 1);
        size_t base = (((size_t)b * 128 + co) * 256 + y) * 256 + xg0;
        float4 xv = *(const float4*)&x[base];
        float mean = g_mean[b * 128 + co];
        float rs = g_rstd[b * 128 + co];
        float nv = nvar[co];
        float cg = g_Cg[co], cb = g_Cb[co];
        float4 o;
        const float* xp = (const float*)&xv;
        float* op = (float*)&o;
        #pragma unroll
        for (int i = 0; i < 4; i++) {
            float ag = 0.f, ab = 0.f;
            #pragma unroll
            for (int k = 0; k < 4; k++) {
                float2 gg = *(const float2*)&g_G4[gb[i][k] + (unsigned)co * 2u];
                ag += gg.x; ab += gg.y;
            }
            unsigned long long v = acc[i][q];
            float gsp = __uint_as_float((unsigned)v);
            float bsp = __uint_as_float((unsigned)(v >> 32));
            float gf = ga * ag + (1.f - ga) * gsp + cg;
            float bf = ba * ab + (1.f - ba) * bsp + cb;
            float val = (xp[i] + nz[i] * nv - mean) * rs;
            op[i] = fmaf(val, gf, val + bf);
        }
        *(float4*)&out[base] = o;
    }
}

// ----------------------------- launch -----------------------------
extern "C" void kernel_launch(void* const* d_in, const int* in_sizes, int n_in,
                              void* d_out, int out_size) {
    const float* x     = (const float*)d_in[0];
    const float* seg   = (const float*)d_in[1];
    const float* sc    = (const float*)d_in[2];
    const float* noise = (const float*)d_in[3];
    const float* nvar  = (const float*)d_in[4];
    const float* bg    = (const float*)d_in[5];
    const float* bb    = (const float*)d_in[6];
    const float* fcw   = (const float*)d_in[7];
    const float* fcb   = (const float*)d_in[8];
    const float* cgw   = (const float*)d_in[9];
    const float* cgb   = (const float*)d_in[10];
    const float* cbw   = (const float*)d_in[11];
    const float* cbb   = (const float*)d_in[12];
    const float* ssw   = (const float*)d_in[13];
    const float* ssb   = (const float*)d_in[14];
    const float* sgw   = (const float*)d_in[15];
    const float* sgb   = (const float*)d_in[16];
    const float* sbw   = (const float*)d_in[17];
    const float* sbb   = (const float*)d_in[18];
    float* out = (float*)d_out;

    k_scal<<<1, 128>>>(bg, bb, cgb, cbb, sgb, sbb);
    k_mu<<<160, 64>>>(sc, fcw, fcb);
    k_cls<<<512, 256>>>(seg);
    k_w1<<<86, 256>>>(ssw);
    k_w2<<<1152, 256>>>(sgw, sbw);
    k_ntr<<<dim3(8, 8, 8), dim3(32, 8)>>>(noise);
    k_stats<<<1024, 256>>>(x, nvar);
    k_lut1<<<160, 128>>>(cgw, cbw);
    k_lut2<<<160, 256>>>();
    k_actv<<<dim3(16, 64, 8), 256>>>(seg, ssb);
    k_main<<<dim3(16, 64, 8), 256>>>(x, nvar, out);
}